// round 16
// baseline (speedup 1.0000x reference)
#include <cuda_runtime.h>
#include <cuda_fp16.h>
#include <cstdint>

#define NTILES 1024

__device__ int g_active[NTILES];
__device__ __align__(16) __half g_wt_h[9 * 256 * 256];        // [pos][f][c] fp16
__device__ __align__(16) __half g_in_h[4 * 224 * 224 * 256];  // input fp16 (active tiles only)

// ---------------- helpers ----------------
__device__ __forceinline__ uint32_t smem_to_u32(const void* p) {
    uint32_t a;
    asm("{ .reg .u64 t; cvta.to.shared.u64 t, %1; cvt.u32.u64 %0, t; }" : "=r"(a) : "l"(p));
    return a;
}
__device__ __forceinline__ void ldsm4(uint32_t* r, uint32_t addr) {
    asm volatile("ldmatrix.sync.aligned.m8n8.x4.shared.b16 {%0,%1,%2,%3}, [%4];"
                 : "=r"(r[0]), "=r"(r[1]), "=r"(r[2]), "=r"(r[3]) : "r"(addr));
}
__device__ __forceinline__ void mma16816(float* d, const uint32_t* a, const uint32_t* b) {
    asm volatile(
        "mma.sync.aligned.m16n8k16.row.col.f32.f16.f16.f32 "
        "{%0,%1,%2,%3}, {%4,%5,%6,%7}, {%8,%9}, {%0,%1,%2,%3};"
        : "+f"(d[0]), "+f"(d[1]), "+f"(d[2]), "+f"(d[3])
        : "r"(a[0]), "r"(a[1]), "r"(a[2]), "r"(a[3]), "r"(b[0]), "r"(b[1]));
}
__device__ __forceinline__ void cpasync16(uint32_t dst, const void* src, int sz) {
    asm volatile("cp.async.cg.shared.global [%0], [%1], 16, %2;\n"
                 :: "r"(dst), "l"(src), "r"(sz) : "memory");
}
__device__ __forceinline__ void cpasync16(uint32_t dst, const void* src) {
    asm volatile("cp.async.cg.shared.global [%0], [%1], 16;\n"
                 :: "r"(dst), "l"(src) : "memory");
}

// ---------------- prep1: active mask + weight transpose ----------------
__global__ void __launch_bounds__(256)
prep1_kernel(const float* __restrict__ mask, const float* __restrict__ wt)
{
    const int b = blockIdx.x;
    const int tid = threadIdx.x;
    if (b < 1024) {
        int n = b >> 8, bi = (b >> 4) & 15, bj = b & 15;
        int j = tid >> 4, i = tid & 15;
        int r = bi * 14 + j - 1;
        int c = bj * 14 + i - 1;
        float v = 0.0f;
        if (r >= 0 && r < 224 && c >= 0 && c < 224) v = mask[(n * 224 + r) * 224 + c];
        __shared__ double s[256];
        s[tid] = (double)v;
        __syncthreads();
        for (int off = 128; off > 0; off >>= 1) {
            if (tid < off) s[tid] += s[tid + off];
            __syncthreads();
        }
        if (tid == 0) g_active[b] = (s[0] > 128.0) ? 1 : 0;
    } else {
        // weight transpose: [pos][c][f] -> [pos][f][c] fp16
        int bb = b - 1024;
        int pos = bb >> 8, f = bb & 255, c = tid;
        float x = wt[((size_t)((pos << 8) | c)) * 256 + f];
        g_wt_h[((size_t)((pos << 8) | f)) * 256 + c] = __float2half_rn(x);
    }
}

// ---------------- prep2: per-tile input convert (active) / output zero (inactive) ----
__global__ void __launch_bounds__(256)
prep2_kernel(const float* __restrict__ in, float* __restrict__ out)
{
    const int tile = blockIdx.x;
    const int n = tile >> 8, bi = (tile >> 4) & 15, bj = tile & 15;
    const int tid = threadIdx.x;

    if (g_active[tile]) {
        // convert this tile's 16x16 halo region, all 256 channels
        int pr = tid >> 4, pc = tid & 15;
        int r = bi * 14 - 1 + pr;
        int c = bj * 14 - 1 + pc;
        if ((unsigned)r < 224u && (unsigned)c < 224u) {
            size_t base = (((size_t)(n * 224 + r)) * 224 + c) * 256;
            const float4* s4 = reinterpret_cast<const float4*>(in + base);
            uint2* d2 = reinterpret_cast<uint2*>(g_in_h + base);
            #pragma unroll 8
            for (int q = 0; q < 64; q++) {
                float4 v = s4[q];
                uint2 hp;
                hp.x = (uint32_t)__half_as_ushort(__float2half_rn(v.x))
                     | ((uint32_t)__half_as_ushort(__float2half_rn(v.y)) << 16);
                hp.y = (uint32_t)__half_as_ushort(__float2half_rn(v.z))
                     | ((uint32_t)__half_as_ushort(__float2half_rn(v.w)) << 16);
                d2[q] = hp;
            }
        }
    } else {
        // zero this tile's output (14x14 x 256)
        float4 z = make_float4(0.f, 0.f, 0.f, 0.f);
        for (int i = tid; i < 196 * 64; i += 256) {
            int px = i >> 6, q = i & 63;
            int oy = px / 14, ox = px - oy * 14;
            size_t o = (((size_t)(n * 224 + bi * 14 + oy)) * 224 + bj * 14 + ox) * 256;
            *reinterpret_cast<float4*>(out + o + q * 4) = z;
        }
    }
}

// ---------------- conv: 2-stage pipeline, cc=32 channels/iter, N=64/CTA ----
// Per stage (53376 B): A = 258 rows x 64B = 16512 B; W = 576 rows x 64B = 36864 B
// 4-seg swizzle: byte(row, seg) = row*64 + (((seg + (row>>1)) & 3) << 4)
#define STAGE_SZ 53376u
#define W_OFF    16512u
#define SMEM_DYN 106752

__device__ __forceinline__ void issue_stage(uint32_t stBase,
                                            int tid, int n, int r0, int c0,
                                            int fq, int cc)
{
    // A: 1024 ops (256 px x 4 segs of 8 ch)
    #pragma unroll
    for (int k = 0; k < 4; k++) {
        int i = tid + (k << 8);
        int px  = i >> 2;
        int seg = i & 3;
        int r = r0 + (px >> 4), c = c0 + (px & 15);
        bool ok = ((unsigned)r < 224u) && ((unsigned)c < 224u);
        int rr = ok ? r : 0, cl = ok ? c : 0;
        const void* src = g_in_h + ((((size_t)(n * 224 + rr)) * 224 + cl) * 256
                                    + cc * 32 + seg * 8);
        uint32_t dst = stBase + (uint32_t)px * 64u
                     + (uint32_t)(((seg + (px >> 1)) & 3) << 4);
        cpasync16(dst, src, ok ? 16 : 0);
    }
    // W: 2304 ops (576 rows x 4 segs)
    #pragma unroll
    for (int k = 0; k < 9; k++) {
        int i = tid + (k << 8);
        int row = i >> 2, seg = i & 3;
        int pos = row >> 6, fl = row & 63;
        const void* src = g_wt_h + (((size_t)(pos * 256 + fq * 64 + fl)) << 8)
                        + cc * 32 + seg * 8;
        uint32_t dst = stBase + W_OFF + (uint32_t)row * 64u
                     + (uint32_t)(((seg + (row >> 1)) & 3) << 4);
        cpasync16(dst, src);
    }
}

__global__ void __launch_bounds__(256, 2)
conv_kernel(const float* __restrict__ bias, float* __restrict__ out)
{
    const int tile = blockIdx.x;
    const int fq   = blockIdx.y;         // 0..3 -> 64 F channels
    const int n = tile >> 8, bi = (tile >> 4) & 15, bj = tile & 15;
    const int tid = threadIdx.x;

    if (!g_active[tile]) return;         // output zeroed by prep2

    extern __shared__ char sm[];
    const uint32_t sb = smem_to_u32(sm);

    const int l   = tid & 31;
    const int wid = tid >> 5;
    const int wm  = wid >> 2;            // 0..1 : M half (112 rows)
    const int wn  = wid & 3;             // 0..3 : 16-F slice within 64

    const int ra0   = wm * 112 + (l & 15);
    const int ahalf = l >> 4;            // A k-seg within k16 (0/1)
    const int rw0   = wn * 16 + ((l >> 4) & 1) * 8 + (l & 7);
    const int whalf = (l >> 3) & 1;      // W k-seg within k16 (0/1)

    const int r0 = bi * 14 - 1;
    const int c0 = bj * 14 - 1;

    // zero the A pad rows (rows 256-257, 128B) in both stages
    if (tid < 64) {
        int s = tid >> 5;
        *reinterpret_cast<uint32_t*>(sm + s * STAGE_SZ + 16384 + (tid & 31) * 4) = 0;
    }

    float acc[7][8];
    #pragma unroll
    for (int t = 0; t < 7; t++)
        #pragma unroll
        for (int j = 0; j < 8; j++) acc[t][j] = 0.f;

    // prologue
    issue_stage(sb, tid, n, r0, c0, fq, 0);
    asm volatile("cp.async.commit_group;\n" ::: "memory");

    for (int cc = 0; cc < 8; cc++) {
        const int p = cc & 1;
        asm volatile("cp.async.wait_group 0;\n" ::: "memory");
        __syncthreads();
        if (cc < 7) {
            issue_stage(sb + (uint32_t)(p ^ 1) * STAGE_SZ, tid, n, r0, c0, fq, cc + 1);
            asm volatile("cp.async.commit_group;\n" ::: "memory");
        }

        const uint32_t stB = sb + (uint32_t)p * STAGE_SZ;
        #pragma unroll
        for (int ks = 0; ks < 2; ks++) {
            // A-fragment reuse across ky: per kx load 9 tiles (rows ra0+kx+16t)
            #pragma unroll 1
            for (int kx = 0; kx < 3; kx++) {
                const int ra = ra0 + kx;
                const int aseg = (ahalf + ks * 2 + (ra >> 1)) & 3;
                const uint32_t aaddr = stB + (uint32_t)ra * 64u
                    + (uint32_t)(aseg << 4);
                uint32_t a[9][4];
                #pragma unroll
                for (int t = 0; t < 9; t++)
                    ldsm4(a[t], aaddr + (uint32_t)t * 1024u);

                #pragma unroll
                for (int ky = 0; ky < 3; ky++) {
                    const int wseg = (whalf + ks * 2 + (rw0 >> 1)) & 3;
                    uint32_t wh[4];
                    ldsm4(wh, stB + W_OFF + (uint32_t)(ky * 3 + kx) * 4096u
                              + (uint32_t)rw0 * 64u + (uint32_t)(wseg << 4));
                    #pragma unroll
                    for (int t = 0; t < 7; t++) {
                        mma16816(acc[t],     a[t + ky], wh);
                        mma16816(acc[t] + 4, a[t + ky], wh + 2);
                    }
                }
            }
        }
    }

    // ---- epilogue: bias + relu + store ----
    const int f0 = fq * 64 + wn * 16 + (l & 3) * 2;
    const float b00 = bias[f0],     b01 = bias[f0 + 1];
    const float b10 = bias[f0 + 8], b11 = bias[f0 + 9];

    #pragma unroll
    for (int t = 0; t < 7; t++) {
        int m_lo = wm * 112 + t * 16 + (l >> 2);
        #pragma unroll
        for (int h = 0; h < 2; h++) {
            int m = m_lo + h * 8;
            int oy = m >> 4, ox = m & 15;
            if (ox < 14) {
                float* p = out + (((size_t)(n * 224 + bi * 14 + oy)) * 224
                                  + bj * 14 + ox) * 256 + f0;
                float2 v0, v1;
                v0.x = fmaxf(acc[t][h * 2 + 0] + b00, 0.f);
                v0.y = fmaxf(acc[t][h * 2 + 1] + b01, 0.f);
                v1.x = fmaxf(acc[t][h * 2 + 4] + b10, 0.f);
                v1.y = fmaxf(acc[t][h * 2 + 5] + b11, 0.f);
                *reinterpret_cast<float2*>(p) = v0;
                *reinterpret_cast<float2*>(p + 8) = v1;
            }
        }
    }
}

extern "C" void kernel_launch(void* const* d_in, const int* in_sizes, int n_in,
                              void* d_out, int out_size) {
    const float* inputs = (const float*)d_in[0];
    const float* mask   = (const float*)d_in[1];
    const float* kernel = (const float*)d_in[2];
    const float* bias   = (const float*)d_in[3];
    float* out = (float*)d_out;

    cudaFuncSetAttribute(conv_kernel, cudaFuncAttributeMaxDynamicSharedMemorySize, SMEM_DYN);

    prep1_kernel<<<3328, 256>>>(mask, kernel);
    prep2_kernel<<<NTILES, 256>>>(inputs, out);
    dim3 grid(NTILES, 4);
    conv_kernel<<<grid, 256, SMEM_DYN>>>(bias, out);
}